// round 2
// baseline (speedup 1.0000x reference)
#include <cuda_runtime.h>

#define DD 64
#define HH 128
#define WW 128
#define NVOX (DD*HH*WW)

// ---- iteration state (static device scratch) ----
__device__ float g_qA[NVOX];
__device__ float g_qB[NVOX];
__device__ float g_du[NVOX];
__device__ float g_coef[4];   // dA0, dA1-dA0, dB0, dB1-dB0

// ---- blur taps (sigma=1, radius 2, normalized) ----
constexpr double c_E05 = 0.60653065971263342426;
constexpr double c_E2  = 0.13533528323661269189;
constexpr double c_KS  = 1.0 + 2.0*c_E05 + 2.0*c_E2;
#define K0F ((float)(1.0   / c_KS))
#define K1F ((float)(c_E05 / c_KS))
#define K2F ((float)(c_E2  / c_KS))

// bilateral: w = sc[d2]*exp(-2*df^2) = 2^(CEXP*df^2 + LSC[d2])
#define CEXP  (-2.8853900817779268f)   // -2*log2(e)
#define LSC1  (-0.3205988979944306f)   // -1/(4.5*ln2)
#define LSC2  (-0.6411977959888612f)
#define LSC3  (-0.9617966939832918f)

#define LOG_SQRT_2PI 0.91893853320467274178f

__device__ __forceinline__ float ex2f(float x) {
    float r; asm("ex2.approx.ftz.f32 %0, %1;" : "=f"(r) : "f"(x)); return r;
}
__device__ __forceinline__ float sigmoidf_fast(float x) {
    return __fdividef(1.0f, 1.0f + ex2f(-1.4426950408889634f * x));
}

// missing-tap mass for blur-of-ones along one axis
__device__ __forceinline__ float axis_sum(int i, int N) {
    float m = 1.f;
    if (i == 0) m -= (K1F + K2F); else if (i == 1) m -= K2F;
    int j = N - 1 - i;
    if (j == 0) m -= (K1F + K2F); else if (j == 1) m -= K2F;
    return m;
}

__global__ void init_kernel(const float* __restrict__ img,
                            const float* __restrict__ h,
                            const float* __restrict__ f1,
                            const float* __restrict__ w0,
                            const float* __restrict__ sw,
                            const float* __restrict__ bw,
                            const float* __restrict__ cm) {
    int i4 = blockIdx.x * blockDim.x + threadIdx.x;
    if (i4 >= NVOX / 4) return;
    if (i4 == 0) {
        float cm0 = cm[2] - cm[0];
        float cm1 = cm[3] - cm[1];
        float dA0 = cm0 * sw[0] + cm1 * sw[2];
        float dA1 = cm0 * sw[1] + cm1 * sw[3];
        float dB0 = cm0 * bw[0] + cm1 * bw[2];
        float dB1 = cm0 * bw[1] + cm1 * bw[3];
        g_coef[0] = dA0; g_coef[1] = dA1 - dA0;
        g_coef[2] = dB0; g_coef[3] = dB1 - dB0;
    }
    float4 I  = ((const float4*)img)[i4];
    float4 h0 = ((const float4*)h)[i4];
    float4 h1 = ((const float4*)h)[i4 + NVOX/4];
    float4 F  = ((const float4*)f1)[i4];
    float wv = w0[0];
    float4 d, du, q;
    d.x = h1.x - h0.x; d.y = h1.y - h0.y; d.z = h1.z - h0.z; d.w = h1.w - h0.w;
    du.x = d.x * (F.x - wv - (-0.5f*I.x*I.x - LOG_SQRT_2PI));
    du.y = d.y * (F.y - wv - (-0.5f*I.y*I.y - LOG_SQRT_2PI));
    du.z = d.z * (F.z - wv - (-0.5f*I.z*I.z - LOG_SQRT_2PI));
    du.w = d.w * (F.w - wv - (-0.5f*I.w*I.w - LOG_SQRT_2PI));
    q.x = sigmoidf_fast(d.x); q.y = sigmoidf_fast(d.y);
    q.z = sigmoidf_fast(d.z); q.w = sigmoidf_fast(d.w);
    ((float4*)g_du)[i4] = du;
    ((float4*)g_qA)[i4] = q;
}

// ---- bilateral core: 27 taps over a 4-wide x quad ----
template<int EDGE>
__device__ __forceinline__ void bilat(
    const float (&sq)[8][12][40], const float (&si)[6][10][40],
    int tz, int ty, int lx0, int gx0, int gy, int gz,
    float acc[4], float den[4], float vs[4])
{
    const float* icrow = &si[1+tz][1+ty][0];
    float4 c4 = *(const float4*)(icrow + lx0);
    const float Ic[4] = {c4.x, c4.y, c4.z, c4.w};

    #pragma unroll
    for (int k = 0; k < 4; k++) { acc[k] = 0.f; den[k] = 0.f; vs[k] = 0.f; }

    float vz[3], vy[3], vx6[6];
    if (EDGE) {
        vz[0] = gz > 0 ? 1.f : 0.f;       vz[1] = 1.f; vz[2] = gz < DD-1 ? 1.f : 0.f;
        vy[0] = gy > 0 ? 1.f : 0.f;       vy[1] = 1.f; vy[2] = gy < HH-1 ? 1.f : 0.f;
        #pragma unroll
        for (int j = 0; j < 6; j++) {
            int g = gx0 - 1 + j;
            vx6[j] = ((unsigned)g < WW) ? 1.f : 0.f;
        }
    }

    const float lsc_tab[4] = {0.f, LSC1, LSC2, LSC3};

    #pragma unroll
    for (int dz = -1; dz <= 1; dz++) {
        #pragma unroll
        for (int dy = -1; dy <= 1; dy++) {
            const float* qr = &sq[2+tz+dz][2+ty+dy][0];
            const float* ir = &si[1+tz+dz][1+ty+dy][0];
            float4 q4 = *(const float4*)(qr + lx0);
            float4 i4 = *(const float4*)(ir + lx0);
            float qv[6] = {qr[lx0-1], q4.x, q4.y, q4.z, q4.w, qr[lx0+4]};
            float iv[6] = {ir[lx0-1], i4.x, i4.y, i4.z, i4.w, ir[lx0+4]};
            const int d2yz = dz*dz + dy*dy;
            const float l_mid  = lsc_tab[d2yz];
            const float l_side = lsc_tab[d2yz + 1];
            float pv[6];
            if (EDGE) {
                float vzy = vz[dz+1] * vy[dy+1];
                #pragma unroll
                for (int j = 0; j < 6; j++) pv[j] = vzy * vx6[j];
            }
            #pragma unroll
            for (int k = 0; k < 4; k++) {
                { // dx = -1
                    float df = Ic[k] - iv[k];
                    float wgt = ex2f(fmaf(df*df, CEXP, l_side));
                    den[k] += wgt;
                    acc[k] = fmaf(wgt, qv[k], acc[k]);
                    if (EDGE) vs[k] = fmaf(wgt, pv[k], vs[k]);
                }
                if (dz == 0 && dy == 0) { // dx = 0 center: w == 1 exactly
                    den[k] += 1.f;
                    acc[k] += qv[k+1];
                    if (EDGE) vs[k] += 1.f;
                } else { // dx = 0
                    float df = Ic[k] - iv[k+1];
                    float wgt = ex2f(fmaf(df*df, CEXP, l_mid));
                    den[k] += wgt;
                    acc[k] = fmaf(wgt, qv[k+1], acc[k]);
                    if (EDGE) vs[k] = fmaf(wgt, pv[k+1], vs[k]);
                }
                { // dx = +1
                    float df = Ic[k] - iv[k+2];
                    float wgt = ex2f(fmaf(df*df, CEXP, l_side));
                    den[k] += wgt;
                    acc[k] = fmaf(wgt, qv[k+2], acc[k]);
                    if (EDGE) vs[k] = fmaf(wgt, pv[k+2], vs[k]);
                }
            }
        }
    }
}

__global__ void __launch_bounds__(256)
iter_kernel(int flip, const float* __restrict__ img)
{
    __shared__ __align__(16) float sq[8][12][40];   // q, z/y halo2, x halo2 at lx [2,38)
    __shared__ __align__(16) float si[6][10][40];   // img, halo1, x at lx [3,37)
    __shared__ __align__(16) float t1[8][12][32];   // x-blurred
    __shared__ __align__(16) float t2[8][8][32];    // xy-blurred

    const float* __restrict__ qprev = flip ? g_qB : g_qA;
    float*       __restrict__ qnext = flip ? g_qA : g_qB;

    const int tx = threadIdx.x;   // 0..7 (x quad)
    const int ty = threadIdx.y;   // 0..7
    const int tz = threadIdx.z;   // 0..3
    const int tid = tx + 8*ty + 64*tz;
    const int w = tid >> 5;
    const int l = tid & 31;
    const int x0 = blockIdx.x * 32;
    const int y0 = blockIdx.y * 8;
    const int z0 = blockIdx.z * 4;

    const int gx0 = x0 + 4*tx;
    const int gy  = y0 + ty;
    const int gz  = z0 + tz;
    const int gi0 = (gz*HH + gy)*WW + gx0;
    const float4 du4 = *(const float4*)&g_du[gi0];
    const float dA0  = g_coef[0];
    const float dA1m = g_coef[1];
    const float dB0  = g_coef[2];
    const float dB1m = g_coef[3];

    // ---- halo load: sq (8 z-planes x 12 rows x 36 cols) ----
    #pragma unroll
    for (int lz = 0; lz < 8; lz++) {
        int gzz = z0 - 2 + lz;
        bool zok = (unsigned)gzz < DD;
        {
            int r = w;
            int gyy = y0 - 2 + r;
            bool zyok = zok && ((unsigned)gyy < HH);
            int rowb = (gzz*HH + gyy)*WW;
            int gxx = x0 - 2 + l;
            float v = 0.f;
            if (zyok && (unsigned)gxx < WW) v = qprev[rowb + gxx];
            sq[lz][r][2+l] = v;
            if (l < 4) {
                int gx2 = x0 + 30 + l;
                float v2 = 0.f;
                if (zyok && (unsigned)gx2 < WW) v2 = qprev[rowb + gx2];
                sq[lz][r][34+l] = v2;
            }
        }
        if (w < 4) {
            int r = w + 8;
            int gyy = y0 - 2 + r;
            bool zyok = zok && ((unsigned)gyy < HH);
            int rowb = (gzz*HH + gyy)*WW;
            int gxx = x0 - 2 + l;
            float v = 0.f;
            if (zyok && (unsigned)gxx < WW) v = qprev[rowb + gxx];
            sq[lz][r][2+l] = v;
            if (l < 4) {
                int gx2 = x0 + 30 + l;
                float v2 = 0.f;
                if (zyok && (unsigned)gx2 < WW) v2 = qprev[rowb + gx2];
                sq[lz][r][34+l] = v2;
            }
        }
    }
    // ---- halo load: si (6 z-planes x 10 rows x 34 cols) ----
    #pragma unroll
    for (int lz = 0; lz < 6; lz++) {
        int gzz = z0 - 1 + lz;
        bool zok = (unsigned)gzz < DD;
        {
            int r = w;
            if (r < 10) {
                int gyy = y0 - 1 + r;
                bool zyok = zok && ((unsigned)gyy < HH);
                int rowb = (gzz*HH + gyy)*WW;
                int gxx = x0 - 1 + l;
                float v = 0.f;
                if (zyok && (unsigned)gxx < WW) v = img[rowb + gxx];
                si[lz][r][3+l] = v;
                if (l < 2) {
                    int gx2 = x0 + 31 + l;
                    float v2 = 0.f;
                    if (zyok && (unsigned)gx2 < WW) v2 = img[rowb + gx2];
                    si[lz][r][35+l] = v2;
                }
            }
        }
        if (w < 2) {
            int r = w + 8;
            int gyy = y0 - 1 + r;
            bool zyok = zok && ((unsigned)gyy < HH);
            int rowb = (gzz*HH + gyy)*WW;
            int gxx = x0 - 1 + l;
            float v = 0.f;
            if (zyok && (unsigned)gxx < WW) v = img[rowb + gxx];
            si[lz][r][3+l] = v;
            if (l < 2) {
                int gx2 = x0 + 31 + l;
                float v2 = 0.f;
                if (zyok && (unsigned)gx2 < WW) v2 = img[rowb + gx2];
                si[lz][r][35+l] = v2;
            }
        }
    }
    __syncthreads();

    // ---- x-blur: 768 quads, 3 per thread ----
    #pragma unroll
    for (int k = 0; k < 3; k++) {
        int e = tid + 256*k;
        int lz = e / 96;
        int r  = e - lz*96;
        int ly = r >> 3;
        int qx = r & 7;
        const float* row = &sq[lz][ly][0];
        float4 a = *(const float4*)(row + 4*qx);
        float4 b = *(const float4*)(row + 4*qx + 4);
        float4 c = *(const float4*)(row + 4*qx + 8);
        float4 o;
        o.x = K2F*(a.z + b.z) + K1F*(a.w + b.y) + K0F*b.x;
        o.y = K2F*(a.w + b.w) + K1F*(b.x + b.z) + K0F*b.y;
        o.z = K2F*(b.x + c.x) + K1F*(b.y + b.w) + K0F*b.z;
        o.w = K2F*(b.y + c.y) + K1F*(b.z + c.x) + K0F*b.w;
        *(float4*)&t1[lz][ly][4*qx] = o;
    }
    __syncthreads();

    // ---- y-blur: 512 quads, 2 per thread ----
    #pragma unroll
    for (int k = 0; k < 2; k++) {
        int e = tid + 256*k;
        int lz = e >> 6;
        int r  = e & 63;
        int yy = r >> 3;
        int qx = r & 7;
        float4 r0 = *(const float4*)&t1[lz][yy  ][4*qx];
        float4 r1 = *(const float4*)&t1[lz][yy+1][4*qx];
        float4 r2 = *(const float4*)&t1[lz][yy+2][4*qx];
        float4 r3 = *(const float4*)&t1[lz][yy+3][4*qx];
        float4 r4 = *(const float4*)&t1[lz][yy+4][4*qx];
        float4 o;
        o.x = K2F*(r0.x+r4.x) + K1F*(r1.x+r3.x) + K0F*r2.x;
        o.y = K2F*(r0.y+r4.y) + K1F*(r1.y+r3.y) + K0F*r2.y;
        o.z = K2F*(r0.z+r4.z) + K1F*(r1.z+r3.z) + K0F*r2.z;
        o.w = K2F*(r0.w+r4.w) + K1F*(r1.w+r3.w) + K0F*r2.w;
        *(float4*)&t2[lz][yy][4*qx] = o;
    }
    __syncthreads();

    // ---- z-blur (per-thread quad) ----
    float4 b0 = *(const float4*)&t2[tz  ][ty][4*tx];
    float4 b1 = *(const float4*)&t2[tz+1][ty][4*tx];
    float4 b2 = *(const float4*)&t2[tz+2][ty][4*tx];
    float4 b3 = *(const float4*)&t2[tz+3][ty][4*tx];
    float4 b4 = *(const float4*)&t2[tz+4][ty][4*tx];
    float sp[4];
    sp[0] = K2F*(b0.x+b4.x) + K1F*(b1.x+b3.x) + K0F*b2.x;
    sp[1] = K2F*(b0.y+b4.y) + K1F*(b1.y+b3.y) + K0F*b2.y;
    sp[2] = K2F*(b0.z+b4.z) + K1F*(b1.z+b3.z) + K0F*b2.z;
    sp[3] = K2F*(b0.w+b4.w) + K1F*(b1.w+b3.w) + K0F*b2.w;

    // ---- bilateral ----
    const int lx0 = 4 + 4*tx;
    float acc[4], den[4], vs[4], pb[4];
    bool edge = (gz == 0) | (gz == DD-1) | (gy == 0) | (gy == HH-1) |
                (gx0 == 0) | (gx0 == WW-4);
    if (!edge) {
        bilat<0>(sq, si, tz, ty, lx0, gx0, gy, gz, acc, den, vs);
        #pragma unroll
        for (int k = 0; k < 4; k++)
            pb[k] = dB0 + dB1m * __fdividef(acc[k], den[k]);
    } else {
        bilat<1>(sq, si, tz, ty, lx0, gx0, gy, gz, acc, den, vs);
        #pragma unroll
        for (int k = 0; k < 4; k++)
            pb[k] = __fdividef(dB0 * vs[k] + dB1m * acc[k], den[k]);
    }

    // ---- combine + write ----
    const float az = axis_sum(gz, DD);
    const float ay = axis_sum(gy, HH);
    const float azy = az * ay;
    const float duv[4] = {du4.x, du4.y, du4.z, du4.w};
    float res[4];
    #pragma unroll
    for (int k = 0; k < 4; k++) {
        float S = azy * axis_sum(gx0 + k, WW);
        float pair = dA0 * S + dA1m * sp[k] + pb[k];
        res[k] = sigmoidf_fast(duv[k] - pair);
    }
    *(float4*)&qnext[gi0] = make_float4(res[0], res[1], res[2], res[3]);
}

__global__ void final_kernel(float* __restrict__ out,
                             const float* __restrict__ f1,
                             int copy_f1) {
    int i4 = blockIdx.x * blockDim.x + threadIdx.x;
    if (i4 >= NVOX / 4) return;
    float4 q = ((const float4*)g_qB)[i4];   // 5 iters end in B
    float4 c0;
    c0.x = 1.f - q.x; c0.y = 1.f - q.y; c0.z = 1.f - q.z; c0.w = 1.f - q.w;
    ((float4*)out)[i4] = c0;
    ((float4*)out)[i4 + NVOX/4] = q;
    if (copy_f1)
        ((float4*)out)[i4 + 2*(NVOX/4)] = ((const float4*)f1)[i4];
}

extern "C" void kernel_launch(void* const* d_in, const int* in_sizes, int n_in,
                              void* d_out, int out_size) {
    const float* img = (const float*)d_in[0];
    const float* h   = (const float*)d_in[1];
    const float* f1  = (const float*)d_in[2];
    const float* w0  = (const float*)d_in[3];
    const float* sw  = (const float*)d_in[4];
    const float* bw  = (const float*)d_in[5];
    const float* cm  = (const float*)d_in[6];
    float* out = (float*)d_out;

    init_kernel<<<NVOX/4/256, 256>>>(img, h, f1, w0, sw, bw, cm);

    dim3 blk(8, 8, 4);
    dim3 grd(WW/32, HH/8, DD/4);
    for (int it = 0; it < 5; it++) {
        iter_kernel<<<grd, blk>>>(it & 1, img);
    }

    int copyf1 = (out_size >= 3 * NVOX) ? 1 : 0;
    final_kernel<<<NVOX/4/256, 256>>>(out, f1, copyf1);
}

// round 3
// speedup vs baseline: 1.0229x; 1.0229x over previous
#include <cuda_runtime.h>

#define DD 64
#define HH 128
#define WW 128
#define NVOX (DD*HH*WW)

// ---- iteration state (static device scratch) ----
__device__ float g_qA[NVOX];
__device__ float g_qB[NVOX];
__device__ float g_du[NVOX];
__device__ float g_coef[4];   // dA0, dA1-dA0, dB0, dB1-dB0

// ---- blur taps (sigma=1, radius 2, normalized) ----
constexpr double c_E05 = 0.60653065971263342426;
constexpr double c_E2  = 0.13533528323661269189;
constexpr double c_KS  = 1.0 + 2.0*c_E05 + 2.0*c_E2;
#define K0F ((float)(1.0   / c_KS))
#define K1F ((float)(c_E05 / c_KS))
#define K2F ((float)(c_E2  / c_KS))

// bilateral: w = sc[d2]*exp(-2*df^2) = 2^(CEXP*df^2 + LSC[d2])
#define CEXP  (-2.8853900817779268f)   // -2*log2(e)
#define LSC1  (-0.3205988979944306f)   // -1/(4.5*ln2)
#define LSC2  (-0.6411977959888612f)
#define LSC3  (-0.9617966939832918f)

#define LOG_SQRT_2PI 0.91893853320467274178f

__device__ __forceinline__ float ex2f(float x) {
    float r; asm("ex2.approx.ftz.f32 %0, %1;" : "=f"(r) : "f"(x)); return r;
}
__device__ __forceinline__ float sigmoidf_fast(float x) {
    return __fdividef(1.0f, 1.0f + ex2f(-1.4426950408889634f * x));
}

// missing-tap mass for blur-of-ones along one axis
__device__ __forceinline__ float axis_sum(int i, int N) {
    float m = 1.f;
    if (i == 0) m -= (K1F + K2F); else if (i == 1) m -= K2F;
    int j = N - 1 - i;
    if (j == 0) m -= (K1F + K2F); else if (j == 1) m -= K2F;
    return m;
}

__global__ void init_kernel(const float* __restrict__ img,
                            const float* __restrict__ h,
                            const float* __restrict__ f1,
                            const float* __restrict__ w0,
                            const float* __restrict__ sw,
                            const float* __restrict__ bw,
                            const float* __restrict__ cm) {
    int i4 = blockIdx.x * blockDim.x + threadIdx.x;
    if (i4 >= NVOX / 4) return;
    if (i4 == 0) {
        float cm0 = cm[2] - cm[0];
        float cm1 = cm[3] - cm[1];
        float dA0 = cm0 * sw[0] + cm1 * sw[2];
        float dA1 = cm0 * sw[1] + cm1 * sw[3];
        float dB0 = cm0 * bw[0] + cm1 * bw[2];
        float dB1 = cm0 * bw[1] + cm1 * bw[3];
        g_coef[0] = dA0; g_coef[1] = dA1 - dA0;
        g_coef[2] = dB0; g_coef[3] = dB1 - dB0;
    }
    float4 I  = ((const float4*)img)[i4];
    float4 h0 = ((const float4*)h)[i4];
    float4 h1 = ((const float4*)h)[i4 + NVOX/4];
    float4 F  = ((const float4*)f1)[i4];
    float wv = w0[0];
    float4 d, du, q;
    d.x = h1.x - h0.x; d.y = h1.y - h0.y; d.z = h1.z - h0.z; d.w = h1.w - h0.w;
    du.x = d.x * (F.x - wv - (-0.5f*I.x*I.x - LOG_SQRT_2PI));
    du.y = d.y * (F.y - wv - (-0.5f*I.y*I.y - LOG_SQRT_2PI));
    du.z = d.z * (F.z - wv - (-0.5f*I.z*I.z - LOG_SQRT_2PI));
    du.w = d.w * (F.w - wv - (-0.5f*I.w*I.w - LOG_SQRT_2PI));
    q.x = sigmoidf_fast(d.x); q.y = sigmoidf_fast(d.y);
    q.z = sigmoidf_fast(d.z); q.w = sigmoidf_fast(d.w);
    ((float4*)g_du)[i4] = du;
    ((float4*)g_qA)[i4] = q;
}

// ---- bilateral core: 27 taps over a 4-wide x quad ----
template<int EDGE>
__device__ __forceinline__ void bilat(
    const float (*sq)[12][40], const float (*si)[10][40],
    int tz, int ty, int lx0, int gx0, int gy, int gz,
    float acc[4], float den[4], float vs[4])
{
    const float* icrow = &si[1+tz][1+ty][0];
    float4 c4 = *(const float4*)(icrow + lx0);
    const float Ic[4] = {c4.x, c4.y, c4.z, c4.w};

    #pragma unroll
    for (int k = 0; k < 4; k++) { acc[k] = 0.f; den[k] = 0.f; vs[k] = 0.f; }

    float vz[3], vy[3], vx6[6];
    if (EDGE) {
        vz[0] = gz > 0 ? 1.f : 0.f;       vz[1] = 1.f; vz[2] = gz < DD-1 ? 1.f : 0.f;
        vy[0] = gy > 0 ? 1.f : 0.f;       vy[1] = 1.f; vy[2] = gy < HH-1 ? 1.f : 0.f;
        #pragma unroll
        for (int j = 0; j < 6; j++) {
            int g = gx0 - 1 + j;
            vx6[j] = ((unsigned)g < WW) ? 1.f : 0.f;
        }
    }

    const float lsc_tab[4] = {0.f, LSC1, LSC2, LSC3};

    #pragma unroll
    for (int dz = -1; dz <= 1; dz++) {
        #pragma unroll
        for (int dy = -1; dy <= 1; dy++) {
            const float* qr = &sq[2+tz+dz][2+ty+dy][0];
            const float* ir = &si[1+tz+dz][1+ty+dy][0];
            float4 q4 = *(const float4*)(qr + lx0);
            float4 i4 = *(const float4*)(ir + lx0);
            float qv[6] = {qr[lx0-1], q4.x, q4.y, q4.z, q4.w, qr[lx0+4]};
            float iv[6] = {ir[lx0-1], i4.x, i4.y, i4.z, i4.w, ir[lx0+4]};
            const int d2yz = dz*dz + dy*dy;
            const float l_mid  = lsc_tab[d2yz];
            const float l_side = lsc_tab[d2yz + 1];
            float pv[6];
            if (EDGE) {
                float vzy = vz[dz+1] * vy[dy+1];
                #pragma unroll
                for (int j = 0; j < 6; j++) pv[j] = vzy * vx6[j];
            }
            #pragma unroll
            for (int k = 0; k < 4; k++) {
                { // dx = -1
                    float df = Ic[k] - iv[k];
                    float wgt = ex2f(fmaf(df*df, CEXP, l_side));
                    den[k] += wgt;
                    acc[k] = fmaf(wgt, qv[k], acc[k]);
                    if (EDGE) vs[k] = fmaf(wgt, pv[k], vs[k]);
                }
                if (dz == 0 && dy == 0) { // dx = 0 center: w == 1 exactly
                    den[k] += 1.f;
                    acc[k] += qv[k+1];
                    if (EDGE) vs[k] += 1.f;
                } else { // dx = 0
                    float df = Ic[k] - iv[k+1];
                    float wgt = ex2f(fmaf(df*df, CEXP, l_mid));
                    den[k] += wgt;
                    acc[k] = fmaf(wgt, qv[k+1], acc[k]);
                    if (EDGE) vs[k] = fmaf(wgt, pv[k+1], vs[k]);
                }
                { // dx = +1
                    float df = Ic[k] - iv[k+2];
                    float wgt = ex2f(fmaf(df*df, CEXP, l_side));
                    den[k] += wgt;
                    acc[k] = fmaf(wgt, qv[k+2], acc[k]);
                    if (EDGE) vs[k] = fmaf(wgt, pv[k+2], vs[k]);
                }
            }
        }
    }
}

__global__ void __launch_bounds__(256, 6)
iter_kernel(int flip, const float* __restrict__ img)
{
    // sq persists all phases. `un` holds si (bilateral phase) then t1/t2 (blur phase).
    __shared__ __align__(16) float sq[8][12][40];   // q: z/y halo2, x halo2 at lx [2,38)
    __shared__ __align__(16) float un[5120];        // 20.0 KB union
    float (*si)[10][40] = (float (*)[10][40])un;          // [6][10][40] = 2400 floats
    float (*t1)[12][32] = (float (*)[12][32])un;          // [8][12][32] = 3072 floats
    float (*t2)[8][32]  = (float (*)[8][32])(un + 3072);  // [8][8][32]  = 2048 floats

    const float* __restrict__ qprev = flip ? g_qB : g_qA;
    float*       __restrict__ qnext = flip ? g_qA : g_qB;

    const int tx = threadIdx.x;   // 0..7 (x quad)
    const int ty = threadIdx.y;   // 0..7
    const int tz = threadIdx.z;   // 0..3
    const int tid = tx + 8*ty + 64*tz;
    const int w = tid >> 5;
    const int l = tid & 31;
    const int x0 = blockIdx.x * 32;
    const int y0 = blockIdx.y * 8;
    const int z0 = blockIdx.z * 4;

    const int gx0 = x0 + 4*tx;
    const int gy  = y0 + ty;
    const int gz  = z0 + tz;
    const int gi0 = (gz*HH + gy)*WW + gx0;

    // ---- halo load: sq (8 z-planes x 12 rows x 36 cols) ----
    #pragma unroll
    for (int lz = 0; lz < 8; lz++) {
        int gzz = z0 - 2 + lz;
        bool zok = (unsigned)gzz < DD;
        {
            int r = w;
            int gyy = y0 - 2 + r;
            bool zyok = zok && ((unsigned)gyy < HH);
            int rowb = (gzz*HH + gyy)*WW;
            int gxx = x0 - 2 + l;
            float v = 0.f;
            if (zyok && (unsigned)gxx < WW) v = qprev[rowb + gxx];
            sq[lz][r][2+l] = v;
            if (l < 4) {
                int gx2 = x0 + 30 + l;
                float v2 = 0.f;
                if (zyok && (unsigned)gx2 < WW) v2 = qprev[rowb + gx2];
                sq[lz][r][34+l] = v2;
            }
        }
        if (w < 4) {
            int r = w + 8;
            int gyy = y0 - 2 + r;
            bool zyok = zok && ((unsigned)gyy < HH);
            int rowb = (gzz*HH + gyy)*WW;
            int gxx = x0 - 2 + l;
            float v = 0.f;
            if (zyok && (unsigned)gxx < WW) v = qprev[rowb + gxx];
            sq[lz][r][2+l] = v;
            if (l < 4) {
                int gx2 = x0 + 30 + l;
                float v2 = 0.f;
                if (zyok && (unsigned)gx2 < WW) v2 = qprev[rowb + gx2];
                sq[lz][r][34+l] = v2;
            }
        }
    }
    // ---- halo load: si (6 z-planes x 10 rows x 34 cols) ----
    #pragma unroll
    for (int lz = 0; lz < 6; lz++) {
        int gzz = z0 - 1 + lz;
        bool zok = (unsigned)gzz < DD;
        {
            int r = w;
            int gyy = y0 - 1 + r;
            bool zyok = zok && ((unsigned)gyy < HH);
            int rowb = (gzz*HH + gyy)*WW;
            int gxx = x0 - 1 + l;
            float v = 0.f;
            if (zyok && (unsigned)gxx < WW) v = img[rowb + gxx];
            si[lz][r][3+l] = v;
            if (l < 2) {
                int gx2 = x0 + 31 + l;
                float v2 = 0.f;
                if (zyok && (unsigned)gx2 < WW) v2 = img[rowb + gx2];
                si[lz][r][35+l] = v2;
            }
        }
        if (w < 2) {
            int r = w + 8;
            int gyy = y0 - 1 + r;
            bool zyok = zok && ((unsigned)gyy < HH);
            int rowb = (gzz*HH + gyy)*WW;
            int gxx = x0 - 1 + l;
            float v = 0.f;
            if (zyok && (unsigned)gxx < WW) v = img[rowb + gxx];
            si[lz][r][3+l] = v;
            if (l < 2) {
                int gx2 = x0 + 31 + l;
                float v2 = 0.f;
                if (zyok && (unsigned)gx2 < WW) v2 = img[rowb + gx2];
                si[lz][r][35+l] = v2;
            }
        }
    }
    __syncthreads();

    // ---- bilateral (si + sq) -> pb[4], before blurs so t1/t2 can reuse si space ----
    const int lx0 = 4 + 4*tx;
    float pb[4];
    {
        float acc[4], den[4], vs[4];
        bool edge = (gz == 0) | (gz == DD-1) | (gy == 0) | (gy == HH-1) |
                    (gx0 == 0) | (gx0 == WW-4);
        if (!edge) {
            bilat<0>(sq, si, tz, ty, lx0, gx0, gy, gz, acc, den, vs);
            float dB0  = g_coef[2];
            float dB1m = g_coef[3];
            #pragma unroll
            for (int k = 0; k < 4; k++)
                pb[k] = dB0 + dB1m * __fdividef(acc[k], den[k]);
        } else {
            bilat<1>(sq, si, tz, ty, lx0, gx0, gy, gz, acc, den, vs);
            float dB0  = g_coef[2];
            float dB1m = g_coef[3];
            #pragma unroll
            for (int k = 0; k < 4; k++)
                pb[k] = __fdividef(dB0 * vs[k] + dB1m * acc[k], den[k]);
        }
    }
    // prefetch per-voxel unary + coefs (latency hidden by blur phases)
    const float4 du4 = *(const float4*)&g_du[gi0];
    const float dA0  = g_coef[0];
    const float dA1m = g_coef[1];
    __syncthreads();   // all si reads done; un[] may be overwritten as t1/t2

    // ---- x-blur: 768 quads, 3 per thread ----
    #pragma unroll
    for (int k = 0; k < 3; k++) {
        int e = tid + 256*k;
        int lz = e / 96;
        int r  = e - lz*96;
        int ly = r >> 3;
        int qx = r & 7;
        const float* row = &sq[lz][ly][0];
        float4 a = *(const float4*)(row + 4*qx);
        float4 b = *(const float4*)(row + 4*qx + 4);
        float4 c = *(const float4*)(row + 4*qx + 8);
        float4 o;
        o.x = K2F*(a.z + b.z) + K1F*(a.w + b.y) + K0F*b.x;
        o.y = K2F*(a.w + b.w) + K1F*(b.x + b.z) + K0F*b.y;
        o.z = K2F*(b.x + c.x) + K1F*(b.y + b.w) + K0F*b.z;
        o.w = K2F*(b.y + c.y) + K1F*(b.z + c.x) + K0F*b.w;
        *(float4*)&t1[lz][ly][4*qx] = o;
    }
    __syncthreads();

    // ---- y-blur: 512 quads, 2 per thread ----
    #pragma unroll
    for (int k = 0; k < 2; k++) {
        int e = tid + 256*k;
        int lz = e >> 6;
        int r  = e & 63;
        int yy = r >> 3;
        int qx = r & 7;
        float4 r0 = *(const float4*)&t1[lz][yy  ][4*qx];
        float4 r1 = *(const float4*)&t1[lz][yy+1][4*qx];
        float4 r2 = *(const float4*)&t1[lz][yy+2][4*qx];
        float4 r3 = *(const float4*)&t1[lz][yy+3][4*qx];
        float4 r4 = *(const float4*)&t1[lz][yy+4][4*qx];
        float4 o;
        o.x = K2F*(r0.x+r4.x) + K1F*(r1.x+r3.x) + K0F*r2.x;
        o.y = K2F*(r0.y+r4.y) + K1F*(r1.y+r3.y) + K0F*r2.y;
        o.z = K2F*(r0.z+r4.z) + K1F*(r1.z+r3.z) + K0F*r2.z;
        o.w = K2F*(r0.w+r4.w) + K1F*(r1.w+r3.w) + K0F*r2.w;
        *(float4*)&t2[lz][yy][4*qx] = o;
    }
    __syncthreads();

    // ---- z-blur (per-thread quad) ----
    float4 b0 = *(const float4*)&t2[tz  ][ty][4*tx];
    float4 b1 = *(const float4*)&t2[tz+1][ty][4*tx];
    float4 b2 = *(const float4*)&t2[tz+2][ty][4*tx];
    float4 b3 = *(const float4*)&t2[tz+3][ty][4*tx];
    float4 b4 = *(const float4*)&t2[tz+4][ty][4*tx];
    float sp[4];
    sp[0] = K2F*(b0.x+b4.x) + K1F*(b1.x+b3.x) + K0F*b2.x;
    sp[1] = K2F*(b0.y+b4.y) + K1F*(b1.y+b3.y) + K0F*b2.y;
    sp[2] = K2F*(b0.z+b4.z) + K1F*(b1.z+b3.z) + K0F*b2.z;
    sp[3] = K2F*(b0.w+b4.w) + K1F*(b1.w+b3.w) + K0F*b2.w;

    // ---- combine + write ----
    const float azy = axis_sum(gz, DD) * axis_sum(gy, HH);
    const float duv[4] = {du4.x, du4.y, du4.z, du4.w};
    float res[4];
    #pragma unroll
    for (int k = 0; k < 4; k++) {
        float S = azy * axis_sum(gx0 + k, WW);
        float pair = dA0 * S + dA1m * sp[k] + pb[k];
        res[k] = sigmoidf_fast(duv[k] - pair);
    }
    *(float4*)&qnext[gi0] = make_float4(res[0], res[1], res[2], res[3]);
}

__global__ void final_kernel(float* __restrict__ out,
                             const float* __restrict__ f1,
                             int copy_f1) {
    int i4 = blockIdx.x * blockDim.x + threadIdx.x;
    if (i4 >= NVOX / 4) return;
    float4 q = ((const float4*)g_qB)[i4];   // 5 iters end in B
    float4 c0;
    c0.x = 1.f - q.x; c0.y = 1.f - q.y; c0.z = 1.f - q.z; c0.w = 1.f - q.w;
    ((float4*)out)[i4] = c0;
    ((float4*)out)[i4 + NVOX/4] = q;
    if (copy_f1)
        ((float4*)out)[i4 + 2*(NVOX/4)] = ((const float4*)f1)[i4];
}

extern "C" void kernel_launch(void* const* d_in, const int* in_sizes, int n_in,
                              void* d_out, int out_size) {
    const float* img = (const float*)d_in[0];
    const float* h   = (const float*)d_in[1];
    const float* f1  = (const float*)d_in[2];
    const float* w0  = (const float*)d_in[3];
    const float* sw  = (const float*)d_in[4];
    const float* bw  = (const float*)d_in[5];
    const float* cm  = (const float*)d_in[6];
    float* out = (float*)d_out;

    init_kernel<<<NVOX/4/256, 256>>>(img, h, f1, w0, sw, bw, cm);

    dim3 blk(8, 8, 4);
    dim3 grd(WW/32, HH/8, DD/4);
    for (int it = 0; it < 5; it++) {
        iter_kernel<<<grd, blk>>>(it & 1, img);
    }

    int copyf1 = (out_size >= 3 * NVOX) ? 1 : 0;
    final_kernel<<<NVOX/4/256, 256>>>(out, f1, copyf1);
}